// round 10
// baseline (speedup 1.0000x reference)
#include <cuda_runtime.h>

#define T_STEPS 8192
#define IN_DIM  128
#define H_DIM   1024
#define NLAYERS 3
#define NCTA    128     // compute CTAs; aggregator is blockIdx.x == NCTA
#define TPB     256
#define NWARP   8

// Static device scratch (allocation-free rule).
__device__ float g_bufA[(size_t)T_STEPS * H_DIM];      // layer 0 output
__device__ float g_bufB[(size_t)T_STEPS * H_DIM];      // layer 1 output
__device__ float g_bufC[(size_t)T_STEPS * H_DIM];      // layer 2 output
__device__ float g_gi[(size_t)T_STEPS * 2 * H_DIM];    // per-layer input projection (reused)
__device__ unsigned g_arrive[NCTA * 8];                // per-CTA flag, 32B apart (own sector)
__device__ unsigned g_mirror[32 * 8];                  // aggregated min, 32 mirrors
__device__ unsigned g_bar_cnt;
__device__ unsigned g_bar_gen;

__device__ __forceinline__ float dot4(float4 a, float4 b) {
    return a.x * b.x + a.y * b.y + a.z * b.z + a.w * b.w;
}
__device__ __forceinline__ float fast_sigmoid(float x) {
    return __fdividef(1.f, 1.f + __expf(-x));
}
__device__ __forceinline__ float fast_tanh(float x) {
    x = fminf(fmaxf(x, -15.f), 15.f);
    float e2 = __expf(2.f * x);
    return __fdividef(e2 - 1.f, e2 + 1.f);
}

__device__ __forceinline__ unsigned ld_acquire_gpu(const unsigned* p) {
    unsigned v;
    asm volatile("ld.acquire.gpu.global.u32 %0, [%1];" : "=r"(v) : "l"(p) : "memory");
    return v;
}
__device__ __forceinline__ void st_release_gpu(unsigned* p, unsigned v) {
    asm volatile("st.release.gpu.global.u32 [%0], %1;" :: "l"(p), "r"(v) : "memory");
}

// Grid barrier among the 128 compute CTAs only (layer boundaries; 3 uses).
__device__ __forceinline__ void grid_barrier(unsigned target) {
    __syncthreads();
    if (threadIdx.x == 0) {
        __threadfence();
        unsigned prev = atomicAdd(&g_bar_cnt, 1u);
        if (prev == NCTA - 1) {
            g_bar_cnt = 0;
            __threadfence();
            *(volatile unsigned*)&g_bar_gen = target;
        } else {
            while (*(volatile unsigned*)&g_bar_gen < target) { }
        }
        __threadfence();
    }
    __syncthreads();
}

__global__ void __launch_bounds__(TPB, 1)
mgu_persistent_kernel(const float* __restrict__ S,
                      const float* __restrict__ h0,
                      const float* __restrict__ w_ih0,
                      const float* __restrict__ w_hh0,
                      const float* __restrict__ b_ih0,
                      const float* __restrict__ b_hh0,
                      const float* __restrict__ w_ih_r,
                      const float* __restrict__ w_hh_r,
                      const float* __restrict__ b_ih_r,
                      const float* __restrict__ b_hh_r,
                      const float* __restrict__ w_out,
                      const float* __restrict__ b_out,
                      float* __restrict__ out)
{
    // ---------------- aggregator CTA ----------------
    // One full warp (lanes 0-31 active: __reduce_min_sync needs the full mask).
    // Exits when min == NLAYERS*T_STEPS, which is strictly after the last
    // consumer target (NLAYERS*T_STEPS - 1), so no consumer can hang.
    if (blockIdx.x == NCTA) {
        if (threadIdx.x < 32) {
            const unsigned total = (unsigned)(NLAYERS * T_STEPS);
            unsigned cur = 0;
            while (cur < total) {
                unsigned vmin = 0xffffffffu;
                #pragma unroll
                for (int k = 0; k < 4; k++) {
                    unsigned v = ld_acquire_gpu(&g_arrive[(threadIdx.x * 4 + k) * 8]);
                    vmin = min(vmin, v);
                }
                vmin = __reduce_min_sync(0xffffffffu, vmin);
                if (vmin > cur) {
                    cur = vmin;
                    st_release_gpu(&g_mirror[threadIdx.x * 8], cur);  // 32 mirrors
                }
            }
        }
        return;
    }

    __shared__ float s_part[2][16][9];   // scan cross-warp partials, padded stride 9
    __shared__ float s_gi[8][16][9];     // gi batch partials (8 timesteps/epoch)
    __shared__ float s_bgi[16];

    const int tid  = threadIdx.x;
    const int wid  = tid >> 5;
    const int lane = tid & 31;
    const int h    = lane >> 4;          // column half within warp chunk
    const int r    = lane & 15;          // row index (0-7: f rows, 8-15: n rows)
    const int c0   = blockIdx.x * 8;     // first h-index owned by this CTA
    const int grow = (r < 8) ? (c0 + r) : (H_DIM + c0 + (r - 8));

    unsigned bgen = 0;

    for (int l = 0; l < NLAYERS; l++) {
        const float *wih, *whh, *bih, *bhh, *xbuf;
        float* obuf;
        if (l == 0) {
            wih = w_ih0; whh = w_hh0; bih = b_ih0; bhh = b_hh0;
            xbuf = S; obuf = g_bufA;
        } else if (l == 1) {
            wih = w_ih_r; whh = w_hh_r; bih = b_ih_r; bhh = b_hh_r;
            xbuf = g_bufA; obuf = g_bufB;
        } else {
            wih = w_ih_r + (size_t)2048 * 1024; whh = w_hh_r + (size_t)2048 * 1024;
            bih = b_ih_r + 2048;                bhh = b_hh_r + 2048;
            xbuf = g_bufB; obuf = g_bufC;
        }

        const float bgi = bih[grow];
        float bhf = 0.f, bhn = 0.f, hreg = 0.f;
        if (tid < 8) {
            bhf  = bhh[c0 + tid];
            bhn  = bhh[H_DIM + c0 + tid];
            hreg = h0[l * H_DIM + c0 + tid];
        }
        if (tid < 16) s_bgi[tid] = bgi;
        __syncthreads();

        float4 wv[16];                   // lane's weight slice (registers)

        // ================= gi phase: g_gi[t][.] = x[t] @ wih.T + b_ih =================
        if (l == 0) {
            #pragma unroll
            for (int j = 0; j < 16; j++)
                wv[j] = reinterpret_cast<const float4*>(wih)[grow * (IN_DIM / 4) + 16 * h + j];
            for (int t = wid; t < T_STEPS; t += NWARP) {
                const float4* vp = reinterpret_cast<const float4*>(xbuf)
                                 + (size_t)t * (IN_DIM / 4) + 16 * h;
                float a0 = 0.f, a1 = 0.f, a2 = 0.f, a3 = 0.f;
                #pragma unroll
                for (int j = 0; j < 16; j += 4) {
                    a0 += dot4(wv[j],     vp[j]);
                    a1 += dot4(wv[j + 1], vp[j + 1]);
                    a2 += dot4(wv[j + 2], vp[j + 2]);
                    a3 += dot4(wv[j + 3], vp[j + 3]);
                }
                float acc = (a0 + a1) + (a2 + a3);
                acc += __shfl_xor_sync(0xffffffffu, acc, 16);
                if (lane < 16)
                    g_gi[(size_t)t * (2 * H_DIM) + grow] = acc + bgi;
            }
        } else {
            #pragma unroll
            for (int j = 0; j < 16; j++)
                wv[j] = reinterpret_cast<const float4*>(wih)[grow * (H_DIM / 4) + 32 * wid + 16 * h + j];
            for (int t0 = 0; t0 < T_STEPS; t0 += 8) {
                #pragma unroll
                for (int dt = 0; dt < 8; dt++) {
                    const float4* vp = reinterpret_cast<const float4*>(xbuf)
                                     + (size_t)(t0 + dt) * (H_DIM / 4) + 32 * wid + 16 * h;
                    float a0 = 0.f, a1 = 0.f, a2 = 0.f, a3 = 0.f;
                    #pragma unroll
                    for (int j = 0; j < 16; j += 4) {
                        a0 += dot4(wv[j],     vp[j]);
                        a1 += dot4(wv[j + 1], vp[j + 1]);
                        a2 += dot4(wv[j + 2], vp[j + 2]);
                        a3 += dot4(wv[j + 3], vp[j + 3]);
                    }
                    float acc = (a0 + a1) + (a2 + a3);
                    acc += __shfl_xor_sync(0xffffffffu, acc, 16);
                    if (lane < 16) s_gi[dt][lane][wid] = acc;
                }
                __syncthreads();
                if (tid < 128) {
                    const int dt  = tid >> 4;
                    const int row = tid & 15;
                    const int gw  = (row < 8) ? (c0 + row) : (H_DIM + c0 + (row - 8));
                    float s = 0.f;
                    #pragma unroll
                    for (int w2 = 0; w2 < 8; w2++) s += s_gi[dt][row][w2];
                    g_gi[(size_t)(t0 + dt) * (2 * H_DIM) + gw] = s + s_bgi[row];
                }
                __syncthreads();
            }
        }
        __syncthreads();   // seal gi before scan reads

        // ================= scan =================
        #pragma unroll
        for (int j = 0; j < 16; j++)
            wv[j] = reinterpret_cast<const float4*>(whh)[grow * (H_DIM / 4) + 32 * wid + 16 * h + j];

        for (int t = 0; t < T_STEPS; t++) {
            // gi prefetch (same-CTA data, no flag dependency)
            float gif = 0.f, gin = 0.f;
            if (tid < 8) {
                gif = g_gi[(size_t)t * (2 * H_DIM) + c0 + tid];
                gin = g_gi[(size_t)t * (2 * H_DIM) + H_DIM + c0 + tid];
            }
            // wait for aggregated min step >= l*T + t
            if (t > 0) {
                const unsigned target = (unsigned)(l * T_STEPS + t);
                if (tid == 0) {
                    while (ld_acquire_gpu(&g_mirror[(blockIdx.x & 31) * 8]) < target) { }
                }
                __syncthreads();   // release CTA; orders subsequent loads
            }

            const float* hsrc = (t == 0) ? (h0 + l * H_DIM)
                                         : (obuf + (size_t)(t - 1) * H_DIM);
            const float4* vp = reinterpret_cast<const float4*>(hsrc) + 32 * wid + 16 * h;
            float a0 = 0.f, a1 = 0.f, a2 = 0.f, a3 = 0.f;
            #pragma unroll
            for (int j = 0; j < 16; j += 4) {
                a0 += dot4(__ldcg(vp + j),     wv[j]);
                a1 += dot4(__ldcg(vp + j + 1), wv[j + 1]);
                a2 += dot4(__ldcg(vp + j + 2), wv[j + 2]);
                a3 += dot4(__ldcg(vp + j + 3), wv[j + 3]);
            }
            float acc = (a0 + a1) + (a2 + a3);
            acc += __shfl_xor_sync(0xffffffffu, acc, 16);
            if (lane < 16) s_part[t & 1][lane][wid] = acc;
            __syncthreads();

            if (tid < 8) {
                float ghf = bhf, ghn = bhn;
                #pragma unroll
                for (int w2 = 0; w2 < 8; w2++) {
                    ghf += s_part[t & 1][tid][w2];
                    ghn += s_part[t & 1][tid + 8][w2];
                }
                float f  = fast_sigmoid(gif + ghf);
                float n  = fast_tanh(gin + f * ghn);
                float hy = n + (1.f - f) * (hreg - n);
                hreg = hy;
                obuf[(size_t)t * H_DIM + c0 + tid] = hy;
            }
            if (wid == 0) __syncwarp();   // teammate stores happen-before the release
            if (tid == 0)
                st_release_gpu(&g_arrive[blockIdx.x * 8],
                               (unsigned)(l * T_STEPS + t + 1));
        }
        grid_barrier(++bgen);   // obuf(l) complete device-wide
    }

    // ================= epilogue: out[t] = bufC[t] . w_out + b_out =================
    float4 wo[8];
    #pragma unroll
    for (int k = 0; k < 8; k++)
        wo[k] = reinterpret_cast<const float4*>(w_out)[lane + 32 * k];
    const float bo = b_out[0];
    for (int tt = wid; tt < 64; tt += NWARP) {
        const int t = blockIdx.x * 64 + tt;
        const float4* xr = reinterpret_cast<const float4*>(g_bufC) + (size_t)t * (H_DIM / 4);
        float a0 = 0.f, a1 = 0.f, a2 = 0.f, a3 = 0.f;
        #pragma unroll
        for (int k = 0; k < 8; k += 4) {
            a0 += dot4(wo[k],     __ldcg(xr + lane + 32 * k));
            a1 += dot4(wo[k + 1], __ldcg(xr + lane + 32 * (k + 1)));
            a2 += dot4(wo[k + 2], __ldcg(xr + lane + 32 * (k + 2)));
            a3 += dot4(wo[k + 3], __ldcg(xr + lane + 32 * (k + 3)));
        }
        float acc = (a0 + a1) + (a2 + a3);
        #pragma unroll
        for (int off = 16; off > 0; off >>= 1)
            acc += __shfl_xor_sync(0xffffffffu, acc, off);
        if (lane == 0) out[t] = acc + bo;
    }
}

// Zero flag/barrier state every launch (graph replays).
__global__ void mgu_reset_kernel() {
    int i = threadIdx.x;
    if (i < NCTA * 8) g_arrive[i] = 0u;
    if (i < 32 * 8)   g_mirror[i] = 0u;
    if (i == 0) { g_bar_cnt = 0u; g_bar_gen = 0u; }
}

extern "C" void kernel_launch(void* const* d_in, const int* in_sizes, int n_in,
                              void* d_out, int out_size) {
    const float* S      = (const float*)d_in[0];
    const float* h0     = (const float*)d_in[1];
    const float* w_ih0  = (const float*)d_in[2];
    const float* w_hh0  = (const float*)d_in[3];
    const float* b_ih0  = (const float*)d_in[4];
    const float* b_hh0  = (const float*)d_in[5];
    const float* w_ih_r = (const float*)d_in[6];
    const float* w_hh_r = (const float*)d_in[7];
    const float* b_ih_r = (const float*)d_in[8];
    const float* b_hh_r = (const float*)d_in[9];
    const float* w_out  = (const float*)d_in[10];
    const float* b_out  = (const float*)d_in[11];
    float* out = (float*)d_out;

    mgu_reset_kernel<<<1, 1024>>>();
    mgu_persistent_kernel<<<NCTA + 1, TPB>>>(
        S, h0, w_ih0, w_hh0, b_ih0, b_hh0,
        w_ih_r, w_hh_r, b_ih_r, b_hh_r, w_out, b_out, out);
}

// round 11
// speedup vs baseline: 1.9694x; 1.9694x over previous
#include <cuda_runtime.h>

#define T_STEPS 8192
#define IN_DIM  128
#define H_DIM   1024
#define NLAYERS 3
#define NCTA    128      // total CTAs (gi/epilogue use all)
#define NSCAN   64       // scan CTAs (bid < NSCAN)
#define TPB     512
#define HPC     16       // h outputs per scan CTA (64*16 = 1024)

// Static device scratch (allocation-free rule).
__device__ float g_bufA[(size_t)T_STEPS * H_DIM];
__device__ float g_bufB[(size_t)T_STEPS * H_DIM];
__device__ float g_bufC[(size_t)T_STEPS * H_DIM];
__device__ float g_gi[(size_t)T_STEPS * 2 * H_DIM];
__device__ unsigned g_slot[NSCAN * 8];       // per-scan-CTA step slot, 32B apart
__device__ unsigned g_bar_cnt;
__device__ unsigned g_bar_gen;

__device__ __forceinline__ float dot4(float4 a, float4 b) {
    return a.x * b.x + a.y * b.y + a.z * b.z + a.w * b.w;
}
__device__ __forceinline__ float fast_sigmoid(float x) {
    return __fdividef(1.f, 1.f + __expf(-x));
}
__device__ __forceinline__ float fast_tanh(float x) {
    x = fminf(fmaxf(x, -15.f), 15.f);
    float e2 = __expf(2.f * x);
    return __fdividef(e2 - 1.f, e2 + 1.f);
}
__device__ __forceinline__ unsigned ld_relaxed_gpu(const unsigned* p) {
    unsigned v;
    asm volatile("ld.relaxed.gpu.global.u32 %0, [%1];" : "=r"(v) : "l"(p) : "memory");
    return v;
}
__device__ __forceinline__ void st_release_gpu(unsigned* p, unsigned v) {
    asm volatile("st.release.gpu.global.u32 [%0], %1;" :: "l"(p), "r"(v) : "memory");
}
__device__ __forceinline__ void fence_acq() {
    asm volatile("fence.acq_rel.gpu;" ::: "memory");
}
// L1-bypassing store: keeps published data out of this SM's L1 (no store-allocate
// staleness for later cross-CTA readers), L2-coherent.
__device__ __forceinline__ void st_cg(float* p, float v) {
    asm volatile("st.global.cg.f32 [%0], %1;" :: "l"(p), "f"(v) : "memory");
}

// Full grid barrier, all 128 CTAs (phase boundaries only; 6 uses).
// __threadfence -> MEMBAR+CCTL.IVALL seals cross-CTA data and wipes L1D.
__device__ __forceinline__ void grid_barrier(unsigned target) {
    __syncthreads();
    if (threadIdx.x == 0) {
        __threadfence();
        unsigned prev = atomicAdd(&g_bar_cnt, 1u);
        if (prev == NCTA - 1) {
            g_bar_cnt = 0;
            __threadfence();
            *(volatile unsigned*)&g_bar_gen = target;
        } else {
            while (*(volatile unsigned*)&g_bar_gen < target) { __nanosleep(256); }
        }
        __threadfence();
    }
    __syncthreads();
}

__global__ void __launch_bounds__(TPB, 1)
mgu_persistent_kernel(const float* __restrict__ S,
                      const float* __restrict__ h0,
                      const float* __restrict__ w_ih0,
                      const float* __restrict__ w_hh0,
                      const float* __restrict__ b_ih0,
                      const float* __restrict__ b_hh0,
                      const float* __restrict__ w_ih_r,
                      const float* __restrict__ w_hh_r,
                      const float* __restrict__ b_ih_r,
                      const float* __restrict__ b_hh_r,
                      const float* __restrict__ w_out,
                      const float* __restrict__ b_out,
                      float* __restrict__ out)
{
    const int tid  = threadIdx.x;
    const int wid  = tid >> 5;        // 16 warps
    const int lane = tid & 31;
    const int bid  = blockIdx.x;

    unsigned bgen = 0;

    for (int l = 0; l < NLAYERS; l++) {
        const float *wih, *whh, *bih, *bhh, *xbuf;
        float* obuf;
        int KIN;
        if (l == 0) {
            wih = w_ih0; whh = w_hh0; bih = b_ih0; bhh = b_hh0;
            xbuf = S; obuf = g_bufA; KIN = IN_DIM;
        } else if (l == 1) {
            wih = w_ih_r; whh = w_hh_r; bih = b_ih_r; bhh = b_hh_r;
            xbuf = g_bufA; obuf = g_bufB; KIN = H_DIM;
        } else {
            wih = w_ih_r + (size_t)2048 * 1024; whh = w_hh_r + (size_t)2048 * 1024;
            bih = b_ih_r + 2048;                bhh = b_hh_r + 2048;
            xbuf = g_bufB; obuf = g_bufC; KIN = H_DIM;
        }

        // ============ gi phase: ALL 128 CTAs, warp-per-row ============
        // CTA covers 16 gi rows: f rows c0g..c0g+7 (warps 0-7), n rows 1024+c0g.. (warps 8-15).
        {
            const int c0g  = bid * 8;
            const int grow = (wid < 8) ? (c0g + wid) : (H_DIM + c0g + (wid - 8));
            const float bias = bih[grow];
            if (KIN == IN_DIM) {
                const float4 w = reinterpret_cast<const float4*>(wih)[grow * (IN_DIM / 4) + lane];
                for (int t = 0; t < T_STEPS; t++) {
                    float4 x = reinterpret_cast<const float4*>(xbuf)[t * (IN_DIM / 4) + lane];
                    float acc = dot4(w, x);
                    #pragma unroll
                    for (int off = 16; off; off >>= 1)
                        acc += __shfl_xor_sync(0xffffffffu, acc, off);
                    if (lane == 0)
                        st_cg(&g_gi[(size_t)t * (2 * H_DIM) + grow], acc + bias);
                }
            } else {
                float4 w[8];
                #pragma unroll
                for (int k = 0; k < 8; k++)
                    w[k] = reinterpret_cast<const float4*>(wih)[grow * (H_DIM / 4) + lane + 32 * k];
                for (int t = 0; t < T_STEPS; t++) {
                    const float4* xp = reinterpret_cast<const float4*>(xbuf)
                                     + (size_t)t * (H_DIM / 4);
                    float a0 = 0.f, a1 = 0.f;
                    #pragma unroll
                    for (int k = 0; k < 8; k += 2) {
                        a0 += dot4(w[k],     xp[lane + 32 * k]);
                        a1 += dot4(w[k + 1], xp[lane + 32 * (k + 1)]);
                    }
                    float acc = a0 + a1;
                    #pragma unroll
                    for (int off = 16; off; off >>= 1)
                        acc += __shfl_xor_sync(0xffffffffu, acc, off);
                    if (lane == 0)
                        st_cg(&g_gi[(size_t)t * (2 * H_DIM) + grow], acc + bias);
                }
            }
        }
        grid_barrier(++bgen);   // gi(l) sealed (incl. L1 invalidate)

        // ============ scan: 64 CTAs, warp-autonomous h-outputs ============
        if (bid < NSCAN) {
            const int c0   = bid * HPC;
            const int hidx = c0 + wid;              // this warp's h output (wid 0..15)

            float4 wf[8], wn[8];
            #pragma unroll
            for (int k = 0; k < 8; k++) {
                wf[k] = reinterpret_cast<const float4*>(whh)[hidx * (H_DIM / 4) + lane + 32 * k];
                wn[k] = reinterpret_cast<const float4*>(whh)[(H_DIM + hidx) * (H_DIM / 4) + lane + 32 * k];
            }
            float bhf = 0.f, bhn = 0.f, hreg = 0.f;
            if (lane == 0) {
                bhf  = bhh[hidx];
                bhn  = bhh[H_DIM + hidx];
                hreg = h0[l * H_DIM + hidx];
            }

            for (int t = 0; t < T_STEPS; t++) {
                // gi prefetch: independent of flags
                float gif = 0.f, gin = 0.f;
                if (lane == 0) {
                    gif = g_gi[(size_t)t * (2 * H_DIM) + hidx];
                    gin = g_gi[(size_t)t * (2 * H_DIM) + H_DIM + hidx];
                }
                // one-hop sync: warp 0 min-reduces the 64 producer slots
                if (t > 0) {
                    if (wid == 0) {
                        const unsigned tgt = (unsigned)(l * T_STEPS + t);
                        unsigned m;
                        do {
                            unsigned a = ld_relaxed_gpu(&g_slot[lane * 8]);
                            unsigned b = ld_relaxed_gpu(&g_slot[(lane + 32) * 8]);
                            m = __reduce_min_sync(0xffffffffu, min(a, b));
                        } while (m < tgt);
                        fence_acq();
                    }
                    __syncthreads();
                }

                const float* hsrc = (t == 0) ? (h0 + l * H_DIM)
                                             : (obuf + (size_t)(t - 1) * H_DIM);
                const float4* vp = reinterpret_cast<const float4*>(hsrc);
                float accf = 0.f, accn = 0.f;
                #pragma unroll
                for (int k = 0; k < 8; k++) {
                    float4 v = vp[lane + 32 * k];   // plain ld: L1-shared across 16 warps
                    accf += dot4(v, wf[k]);
                    accn += dot4(v, wn[k]);
                }
                #pragma unroll
                for (int off = 16; off; off >>= 1) {
                    accf += __shfl_xor_sync(0xffffffffu, accf, off);
                    accn += __shfl_xor_sync(0xffffffffu, accn, off);
                }
                if (lane == 0) {
                    float f  = fast_sigmoid(gif + accf + bhf);
                    float n  = fast_tanh(gin + f * (accn + bhn));
                    float hy = n + (1.f - f) * (hreg - n);
                    hreg = hy;
                    st_cg(obuf + (size_t)t * H_DIM + hidx, hy);   // bypass L1
                }
                __syncthreads();                 // all 16 warps' stores done
                if (tid == 0)
                    st_release_gpu(&g_slot[bid * 8], (unsigned)(l * T_STEPS + t + 1));
            }
        }
        grid_barrier(++bgen);   // obuf(l) sealed for gi(l+1)/epilogue
    }

    // ============ epilogue: out[t] = bufC[t].w_out + b_out (all CTAs) ============
    float4 wo[8];
    #pragma unroll
    for (int k = 0; k < 8; k++)
        wo[k] = reinterpret_cast<const float4*>(w_out)[lane + 32 * k];
    const float bo = b_out[0];
    for (int t = bid * 16 + wid; t < T_STEPS; t += NCTA * 16) {
        const float4* xr = reinterpret_cast<const float4*>(g_bufC) + (size_t)t * (H_DIM / 4);
        float a0 = 0.f, a1 = 0.f;
        #pragma unroll
        for (int k = 0; k < 8; k += 2) {
            a0 += dot4(wo[k],     xr[lane + 32 * k]);
            a1 += dot4(wo[k + 1], xr[lane + 32 * (k + 1)]);
        }
        float acc = a0 + a1;
        #pragma unroll
        for (int off = 16; off; off >>= 1)
            acc += __shfl_xor_sync(0xffffffffu, acc, off);
        if (lane == 0) out[t] = acc + bo;
    }
}

// Zero slot/barrier state every launch (graph replays).
__global__ void mgu_reset_kernel() {
    int i = threadIdx.x;
    if (i < NSCAN * 8) g_slot[i] = 0u;
    if (i == 0) { g_bar_cnt = 0u; g_bar_gen = 0u; }
}

extern "C" void kernel_launch(void* const* d_in, const int* in_sizes, int n_in,
                              void* d_out, int out_size) {
    const float* S      = (const float*)d_in[0];
    const float* h0     = (const float*)d_in[1];
    const float* w_ih0  = (const float*)d_in[2];
    const float* w_hh0  = (const float*)d_in[3];
    const float* b_ih0  = (const float*)d_in[4];
    const float* b_hh0  = (const float*)d_in[5];
    const float* w_ih_r = (const float*)d_in[6];
    const float* w_hh_r = (const float*)d_in[7];
    const float* b_ih_r = (const float*)d_in[8];
    const float* b_hh_r = (const float*)d_in[9];
    const float* w_out  = (const float*)d_in[10];
    const float* b_out  = (const float*)d_in[11];
    float* out = (float*)d_out;

    mgu_reset_kernel<<<1, 1024>>>();
    mgu_persistent_kernel<<<NCTA, TPB>>>(
        S, h0, w_ih0, w_hh0, b_ih0, b_hh0,
        w_ih_r, w_hh_r, b_ih_r, b_hh_r, w_out, b_out, out);
}

// round 13
// speedup vs baseline: 2.7592x; 1.4010x over previous
#include <cuda_runtime.h>

#define T_STEPS 8192
#define IN_DIM  128
#define H_DIM   1024
#define NCTA    128
#define NGRP    64        // CTAs per layer group
#define TPB     512
#define HPC     16        // h outputs per CTA

// Static device scratch (allocation-free rule).
__device__ float g_bufA[(size_t)T_STEPS * H_DIM];
__device__ float g_bufB[(size_t)T_STEPS * H_DIM];
__device__ float g_bufC[(size_t)T_STEPS * H_DIM];
__device__ unsigned g_slot[NCTA * 8];     // per-CTA release slot, 32B apart
__device__ unsigned g_bar_cnt;
__device__ unsigned g_bar_gen;

__device__ __forceinline__ float dot4(float4 a, float4 b) {
    return a.x * b.x + a.y * b.y + a.z * b.z + a.w * b.w;
}
__device__ __forceinline__ float fast_sigmoid(float x) {
    return __fdividef(1.f, 1.f + __expf(-x));
}
__device__ __forceinline__ float fast_tanh(float x) {
    x = fminf(fmaxf(x, -15.f), 15.f);
    float e2 = __expf(2.f * x);
    return __fdividef(e2 - 1.f, e2 + 1.f);
}
__device__ __forceinline__ unsigned ld_acquire_gpu(const unsigned* p) {
    unsigned v;
    asm volatile("ld.acquire.gpu.global.u32 %0, [%1];" : "=r"(v) : "l"(p) : "memory");
    return v;
}
__device__ __forceinline__ void st_release_gpu(unsigned* p, unsigned v) {
    asm volatile("st.release.gpu.global.u32 [%0], %1;" :: "l"(p), "r"(v) : "memory");
}
__device__ __forceinline__ void st_cg(float* p, float v) {
    asm volatile("st.global.cg.f32 [%0], %1;" :: "l"(p), "f"(v) : "memory");
}

// Full grid barrier, all 128 CTAs (phase boundaries; 2 uses).
__device__ __forceinline__ void grid_barrier(unsigned target) {
    __syncthreads();
    if (threadIdx.x == 0) {
        __threadfence();
        unsigned prev = atomicAdd(&g_bar_cnt, 1u);
        if (prev == NCTA - 1) {
            g_bar_cnt = 0;
            __threadfence();
            *(volatile unsigned*)&g_bar_gen = target;
        } else {
            while (*(volatile unsigned*)&g_bar_gen < target) { __nanosleep(256); }
        }
        __threadfence();
    }
    __syncthreads();
}

// One layer scan with self-computed gi.
// W_hh rows (f,n) for this warp's output in registers; W_ih rows (2*HPC) in SMEM.
// Slot semantics: slot == base + k  <=>  that CTA published h(k-1) of its layer.
// Consumer tick t needs: own-group min >= own_base + t; feeder min >= t + 1.
// Tick order: [poll feeder] -> gi -> [poll own] -> gh -> combine -> publish.
template<int KIN, bool FPOLL>
__device__ void scan_selfgi(const float* __restrict__ whh,
                            const float* __restrict__ wih,
                            const float* __restrict__ bhh,
                            const float* __restrict__ bih,
                            const float* __restrict__ xfeed,  // [T][KIN]
                            float* __restrict__ obuf,
                            const float* __restrict__ h0l,
                            int c0, unsigned own_base,
                            int own_slot0, int feed_slot0, int my_slot,
                            float* s_wihm)
{
    const int tid  = threadIdx.x;
    const int wid  = tid >> 5;
    const int lane = tid & 31;
    const int hidx = c0 + wid;                 // this warp's h output
    constexpr int KI4 = KIN / 4;

    // W_hh rows -> registers
    float4 wf[8], wn[8];
    #pragma unroll
    for (int k = 0; k < 8; k++) {
        wf[k] = reinterpret_cast<const float4*>(whh)[hidx * (H_DIM / 4) + lane + 32 * k];
        wn[k] = reinterpret_cast<const float4*>(whh)[(H_DIM + hidx) * (H_DIM / 4) + lane + 32 * k];
    }
    // W_ih rows (2*HPC x KIN) -> SMEM (coalesced)
    for (int i = tid; i < 2 * HPC * KI4; i += TPB) {
        int row = i / KI4, col4 = i - row * KI4;
        int grow = (row < HPC) ? (c0 + row) : (H_DIM + c0 + (row - HPC));
        reinterpret_cast<float4*>(s_wihm)[i] =
            reinterpret_cast<const float4*>(wih)[grow * KI4 + col4];
    }
    float bhf = 0.f, bhn = 0.f, bif = 0.f, bin_ = 0.f, hreg = 0.f;
    if (lane == 0) {
        bhf  = bhh[hidx];
        bhn  = bhh[H_DIM + hidx];
        bif  = bih[hidx];
        bin_ = bih[H_DIM + hidx];
        hreg = h0l[hidx];
    }
    __syncthreads();   // SMEM weights ready

    const float4* sw = reinterpret_cast<const float4*>(s_wihm);

    for (int t = 0; t < T_STEPS; t++) {
        // ---- poll feeder first (only L1 needs it): xfeed[t] ready? ----
        if (FPOLL) {
            if (wid == 0) {
                const unsigned ftgt = (unsigned)(t + 1);
                for (;;) {
                    unsigned f = min(ld_acquire_gpu(&g_slot[(feed_slot0 + lane) * 8]),
                                     ld_acquire_gpu(&g_slot[(feed_slot0 + 32 + lane) * 8]));
                    if (__reduce_min_sync(0xffffffffu, f) >= ftgt) break;
                }
            }
            __syncthreads();
        }

        // ---- gi = W_ih rows . xfeed[t] (input independent of own-group wait) ----
        const float4* xp = reinterpret_cast<const float4*>(xfeed) + (size_t)t * KI4;
        float gifa = 0.f, gina = 0.f;
        #pragma unroll
        for (int k = 0; k < KI4 / 32; k++) {
            float4 x = xp[lane + 32 * k];
            gifa += dot4(sw[wid * KI4 + lane + 32 * k], x);
            gina += dot4(sw[(HPC + wid) * KI4 + lane + 32 * k], x);
        }

        // ---- poll own group: h(t-1) fully published? ----
        if (t > 0) {
            if (wid == 0) {
                const unsigned otgt = own_base + (unsigned)t;
                for (;;) {
                    unsigned o = min(ld_acquire_gpu(&g_slot[(own_slot0 + lane) * 8]),
                                     ld_acquire_gpu(&g_slot[(own_slot0 + 32 + lane) * 8]));
                    if (__reduce_min_sync(0xffffffffu, o) >= otgt) break;
                }
            }
            __syncthreads();
        }

        // ---- gh = W_hh rows . h(t-1) (register weights) ----
        const float* hsrc = (t == 0) ? h0l : (obuf + (size_t)(t - 1) * H_DIM);
        const float4* vp = reinterpret_cast<const float4*>(hsrc);
        float af = 0.f, an = 0.f;
        #pragma unroll
        for (int k = 0; k < 8; k++) {
            float4 v = vp[lane + 32 * k];
            af += dot4(v, wf[k]);
            an += dot4(v, wn[k]);
        }
        #pragma unroll
        for (int off = 16; off; off >>= 1) {
            af   += __shfl_xor_sync(0xffffffffu, af, off);
            an   += __shfl_xor_sync(0xffffffffu, an, off);
            gifa += __shfl_xor_sync(0xffffffffu, gifa, off);
            gina += __shfl_xor_sync(0xffffffffu, gina, off);
        }
        if (lane == 0) {
            float f  = fast_sigmoid(gifa + bif + af + bhf);
            float n  = fast_tanh(gina + bin_ + f * (an + bhn));
            float hy = n + (1.f - f) * (hreg - n);
            hreg = hy;
            st_cg(obuf + (size_t)t * H_DIM + hidx, hy);   // bypass L1
        }
        __syncthreads();   // all 16 warps' h stores done
        if (tid == 0)
            st_release_gpu(&g_slot[my_slot * 8], own_base + (unsigned)(t + 1));
    }
}

__global__ void __launch_bounds__(TPB, 1)
mgu_persistent_kernel(const float* __restrict__ S,
                      const float* __restrict__ h0,
                      const float* __restrict__ w_ih0,
                      const float* __restrict__ w_hh0,
                      const float* __restrict__ b_ih0,
                      const float* __restrict__ b_hh0,
                      const float* __restrict__ w_ih_r,
                      const float* __restrict__ w_hh_r,
                      const float* __restrict__ b_ih_r,
                      const float* __restrict__ b_hh_r,
                      const float* __restrict__ w_out,
                      const float* __restrict__ b_out,
                      float* __restrict__ out)
{
    extern __shared__ float s_wih[];   // 32 rows x up-to-1024 floats (128KB)

    const int tid  = threadIdx.x;
    const int wid  = tid >> 5;
    const int lane = tid & 31;
    const int bid  = blockIdx.x;
    const bool grpB = (bid >= NGRP);

    const float* wih2 = w_ih_r + (size_t)2048 * 1024;
    const float* whh2 = w_hh_r + (size_t)2048 * 1024;
    const float* bih2 = b_ih_r + 2048;
    const float* bhh2 = b_hh_r + 2048;

    // ===== Phase A': L0 (CTAs 0-63) || L1 (CTAs 64-127) =====
    if (!grpB) {
        scan_selfgi<IN_DIM, false>(w_hh0, w_ih0, b_hh0, b_ih0,
                                   S, g_bufA, h0,
                                   bid * HPC, 0u,
                                   /*own_slot0=*/0, /*feed_slot0=*/0, /*my_slot=*/bid,
                                   s_wih);
    } else {
        scan_selfgi<H_DIM, true>(w_hh_r, w_ih_r, b_hh_r, b_ih_r,
                                 g_bufA, g_bufB, h0 + H_DIM,
                                 (bid - NGRP) * HPC, 0u,
                                 /*own_slot0=*/NGRP, /*feed_slot0=*/0, /*my_slot=*/bid,
                                 s_wih);
    }
    grid_barrier(1);   // bufA, bufB sealed; L1 invalidated

    // ===== Phase C: L2 on CTAs 64-127 (slots continue at base 8192) =====
    if (grpB) {
        scan_selfgi<H_DIM, false>(whh2, wih2, bhh2, bih2,
                                  g_bufB, g_bufC, h0 + 2 * H_DIM,
                                  (bid - NGRP) * HPC, (unsigned)T_STEPS,
                                  /*own_slot0=*/NGRP, /*feed_slot0=*/0, /*my_slot=*/bid,
                                  s_wih);
    }
    grid_barrier(2);   // bufC sealed

    // ===== Epilogue: out[t] = bufC[t].w_out + b_out (all CTAs) =====
    float4 wo[8];
    #pragma unroll
    for (int k = 0; k < 8; k++)
        wo[k] = reinterpret_cast<const float4*>(w_out)[lane + 32 * k];
    const float bo = b_out[0];
    for (int t = bid * 16 + wid; t < T_STEPS; t += NCTA * 16) {
        const float4* xr = reinterpret_cast<const float4*>(g_bufC) + (size_t)t * (H_DIM / 4);
        float a0 = 0.f, a1 = 0.f;
        #pragma unroll
        for (int k = 0; k < 8; k += 2) {
            a0 += dot4(wo[k],     __ldcg(xr + lane + 32 * k));
            a1 += dot4(wo[k + 1], __ldcg(xr + lane + 32 * (k + 1)));
        }
        float acc = a0 + a1;
        #pragma unroll
        for (int off = 16; off; off >>= 1)
            acc += __shfl_xor_sync(0xffffffffu, acc, off);
        if (lane == 0) out[t] = acc + bo;
    }
}

// Zero slot/barrier state every launch (graph replays).
__global__ void mgu_reset_kernel() {
    int i = threadIdx.x;
    if (i < NCTA * 8) g_slot[i] = 0u;
    if (i == 0) { g_bar_cnt = 0u; g_bar_gen = 0u; }
}

extern "C" void kernel_launch(void* const* d_in, const int* in_sizes, int n_in,
                              void* d_out, int out_size) {
    const float* S      = (const float*)d_in[0];
    const float* h0     = (const float*)d_in[1];
    const float* w_ih0  = (const float*)d_in[2];
    const float* w_hh0  = (const float*)d_in[3];
    const float* b_ih0  = (const float*)d_in[4];
    const float* b_hh0  = (const float*)d_in[5];
    const float* w_ih_r = (const float*)d_in[6];
    const float* w_hh_r = (const float*)d_in[7];
    const float* b_ih_r = (const float*)d_in[8];
    const float* b_hh_r = (const float*)d_in[9];
    const float* w_out  = (const float*)d_in[10];
    const float* b_out  = (const float*)d_in[11];
    float* out = (float*)d_out;

    const int smem_bytes = 2 * HPC * H_DIM * (int)sizeof(float);  // 128KB
    cudaFuncSetAttribute(mgu_persistent_kernel,
                         cudaFuncAttributeMaxDynamicSharedMemorySize, smem_bytes);

    mgu_reset_kernel<<<1, 1024>>>();
    mgu_persistent_kernel<<<NCTA, TPB, smem_bytes>>>(
        S, h0, w_ih0, w_hh0, b_ih0, b_hh0,
        w_ih_r, w_hh_r, b_ih_r, b_hh_r, w_out, b_out, out);
}